// round 12
// baseline (speedup 1.0000x reference)
#include <cuda_runtime.h>
#include <math.h>

// ---- problem constants ----
#define NFFT      512
#define HOP       256
#define NBIN      19      // rfft bins 13..31  (400 <= f < 1000 Hz, df = 31.25)
#define BIN0      13
#define NANG      18001
#define MICS      4
#define NFRM      4       // EST_NUM frames, t = 120..123
#define SAMPLE_OFF 30464  // first sample used = 119*256

// per-bin projector coefficients [q0,q1r,q1i,q2r,q2i,q3r,q3i,pad]
__device__ float gQ[NBIN * 8];

// ---- one complex Jacobi rotation, 4-lane cooperative (lane r = row r) ----
// Compile-time (p,q). All shuffles over mask 0xF (lanes 0..3 only active).
#define ROT4(p, q) do {                                                        \
    float gr  = __shfl_sync(0xFu, ar[q], p);                                   \
    float gi  = __shfl_sync(0xFu, ai[q], p);                                   \
    float app = __shfl_sync(0xFu, ar[p], p);                                   \
    float aqq = __shfl_sync(0xFu, ar[q], q);                                   \
    float g2  = fmaf(gr, gr, gi * gi);                                         \
    if (g2 >= thr) {   /* uniform across the 4 lanes */                        \
        float inv_g = rsqrtf(g2);                                              \
        float er = gr * inv_g, ei = gi * inv_g;                                \
        float tau = (aqq - app) * (0.5f * inv_g);                              \
        float t2  = fmaf(tau, tau, 1.f);                                       \
        float root = t2 * rsqrtf(t2);                                          \
        float tt = __fdividef((tau >= 0.f) ? -1.f : 1.f, fabsf(tau) + root);   \
        float cc = rsqrtf(fmaf(tt, tt, 1.f));                                  \
        float ss = tt * cc;                                                    \
        float se_r = ss * er, se_i = ss * ei;                                  \
        float ce_r = cc * er, ce_i = cc * ei;                                  \
        /* A <- A R : columns p,q of own row */                                \
        { float pr = ar[p], pi = ai[p], qr = ar[q], qi = ai[q];                \
          ar[p] =  pr*cc + qr*se_r + qi*se_i;                                  \
          ai[p] =  pi*cc - qr*se_i + qi*se_r;                                  \
          ar[q] = -pr*ss + qr*ce_r + qi*ce_i;                                  \
          ai[q] = -pi*ss - qr*ce_i + qi*ce_r; }                                \
        /* A <- R^H A : rows p,q (post-col-update, matching original order) */ \
        _Pragma("unroll")                                                      \
        for (int j = 0; j < 4; j++) {                                          \
            float opr = __shfl_sync(0xFu, ar[j], p);                           \
            float opi = __shfl_sync(0xFu, ai[j], p);                           \
            float oqr = __shfl_sync(0xFu, ar[j], q);                           \
            float oqi = __shfl_sync(0xFu, ai[j], q);                           \
            if (r == p) {                                                      \
                ar[j] = cc*opr + se_r*oqr - se_i*oqi;                          \
                ai[j] = cc*opi + se_r*oqi + se_i*oqr;                          \
            } else if (r == q) {                                               \
                ar[j] = -ss*opr + ce_r*oqr - ce_i*oqi;                         \
                ai[j] = -ss*opi + ce_r*oqi + ce_i*oqr;                         \
            }                                                                  \
        }                                                                      \
        /* V <- V R : columns p,q of own row */                                \
        { float pr = vr[p], pi = vi[p], qr = vr[q], qi = vi[q];                \
          vr[p] =  pr*cc + qr*se_r + qi*se_i;                                  \
          vi[p] =  pi*cc - qr*se_i + qi*se_r;                                  \
          vr[q] = -pr*ss + qr*ce_r + qi*ce_i;                                  \
          vi[q] = -pi*ss - qr*ce_i + qi*ce_r; }                                \
    }                                                                          \
} while (0)

// ============================================================
// Kernel 1: bin-per-block fused DFT + eigen. 19 blocks x 512 thr.
//   16 warps: windowed 512-tap DFT for (t,c) of this block's bin.
//   then lanes 0..3 of warp 0: cooperative 4x4 complex Jacobi,
//   noise projector -> gQ[bin].
// ============================================================
__global__ void __launch_bounds__(512, 1) k_dft_eig(const float* __restrict__ x)
{
    __shared__ float2 sX[NFRM * MICS];    // X[t][c] for this bin
    __shared__ float  sV[4][8];           // eigenvector rows for the tail

    const int bin = blockIdx.x + BIN0;
    const int tid = threadIdx.x;
    const int w   = tid >> 5;             // 0..15  -> (t,c)
    const int l   = tid & 31;
    const int t   = w >> 2;
    const int c   = w & 3;

    // ---------- DFT ----------
    {
        const float ANG = -0.012271846303085130f;          // -2*pi/512
        float c1, s1, cs, ss;
        __sincosf((float)((bin * l)  & 511) * ANG, &s1, &c1);
        __sincosf((float)((bin * 32) & 511) * ANG, &ss, &cs);

        const float* px = x + ((size_t)SAMPLE_OFF + (size_t)t * HOP) * MICS + c;

        float re = 0.f, im = 0.f;
        #pragma unroll
        for (int j = 0; j < 16; j++) {
            int n = l + 32 * j;
            float v = px[n * MICS] * __sinf((float)n * (float)(M_PI / 512.0));
            re = fmaf(v, c1, re);
            im = fmaf(v, s1, im);
            float cn = fmaf(c1, cs, -s1 * ss);
            float sn = fmaf(s1, cs,  c1 * ss);
            c1 = cn; s1 = sn;
        }
        #pragma unroll
        for (int off = 16; off; off >>= 1) {
            re += __shfl_down_sync(0xffffffffu, re, off);
            im += __shfl_down_sync(0xffffffffu, im, off);
        }
        if (l == 0) sX[w] = make_float2(re, im);
    }
    __syncthreads();

    // ---------- eigen: lanes 0..3 of warp 0, lane r = row r ----------
    if (tid < 4) {
        const int r = tid;
        float ar[4], ai[4], vr[4], vi[4];

        // row r of A = (1/4) sum_t X[t][r] conj(X[t][d])
        #pragma unroll
        for (int d = 0; d < 4; d++) {
            float sr = 0.f, si = 0.f;
            #pragma unroll
            for (int tt2 = 0; tt2 < NFRM; tt2++) {
                float2 a = sX[tt2 * MICS + r];
                float2 b = sX[tt2 * MICS + d];
                sr = fmaf(a.x, b.x, fmaf(a.y, b.y, sr));
                si = fmaf(a.y, b.x, fmaf(-a.x, b.y, si));
            }
            ar[d] = 0.25f * sr;
            ai[d] = 0.25f * si;
        }
        // exact-zero diagonal imag, identity V (compile-time indexing only)
        ai[0] = (r == 0) ? 0.f : ai[0];
        ai[1] = (r == 1) ? 0.f : ai[1];
        ai[2] = (r == 2) ? 0.f : ai[2];
        ai[3] = (r == 3) ? 0.f : ai[3];
        #pragma unroll
        for (int j = 0; j < 4; j++) { vr[j] = (j == r) ? 1.f : 0.f; vi[j] = 0.f; }

        // trace across lanes (each lane's diagonal element, butterfly sum)
        float dg = (r == 0) ? ar[0] : (r == 1) ? ar[1] : (r == 2) ? ar[2] : ar[3];
        float tsum = dg + __shfl_xor_sync(0xFu, dg, 1);
        float trace = tsum + __shfl_xor_sync(0xFu, tsum, 2);
        float thr = trace * trace * 1e-14f + 1e-30f;

        for (int sweep = 0; sweep < 5; sweep++) {
            ROT4(0,1); ROT4(2,3);
            ROT4(0,2); ROT4(1,3);
            ROT4(0,3); ROT4(1,2);
        }

        // eigenvalues (diagonal) gathered to all lanes
        float evr = (r == 0) ? ar[0] : (r == 1) ? ar[1] : (r == 2) ? ar[2] : ar[3];
        float ev0 = __shfl_sync(0xFu, evr, 0);
        float ev1 = __shfl_sync(0xFu, evr, 1);
        float ev2 = __shfl_sync(0xFu, evr, 2);
        float ev3 = __shfl_sync(0xFu, evr, 3);

        // stash V rows for the scalar tail
        #pragma unroll
        for (int j = 0; j < 4; j++) { sV[r][j] = vr[j]; sV[r][4 + j] = vi[j]; }
        __syncwarp(0xFu);

        if (r == 0) {
            // noise-subspace weights: two smallest eigenvalues
            int r0 = (ev1 <  ev0) + (ev2 <  ev0) + (ev3 <  ev0);
            int r1 = (ev0 <= ev1) + (ev2 <  ev1) + (ev3 <  ev1);
            int r2 = (ev0 <= ev2) + (ev1 <= ev2) + (ev3 <  ev2);
            int r3 = (ev0 <= ev3) + (ev1 <= ev3) + (ev2 <= ev3);
            float wj[4];
            wj[0] = (r0 < 2) ? 1.f : 0.f;
            wj[1] = (r1 < 2) ? 1.f : 0.f;
            wj[2] = (r2 < 2) ? 1.f : 0.f;
            wj[3] = (r3 < 2) ? 1.f : 0.f;

            float Pd = 0.f;
            #pragma unroll
            for (int j = 0; j < 4; j++) {
                float s = 0.f;
                #pragma unroll
                for (int cc2 = 0; cc2 < 4; cc2++)
                    s = fmaf(sV[cc2][j], sV[cc2][j], fmaf(sV[cc2][4+j], sV[cc2][4+j], s));
                Pd = fmaf(wj[j], s, Pd);
            }
            #define PCD(cc2, dd, PR, PI)                                             \
                float PR = 0.f, PI = 0.f;                                            \
                _Pragma("unroll")                                                    \
                for (int j = 0; j < 4; j++) {                                        \
                    float pr = fmaf(sV[cc2][j], sV[dd][j], sV[cc2][4+j]*sV[dd][4+j]);\
                    float pi = fmaf(sV[cc2][4+j], sV[dd][j], -sV[cc2][j]*sV[dd][4+j]);\
                    PR = fmaf(wj[j], pr, PR);                                        \
                    PI = fmaf(wj[j], pi, PI);                                        \
                }
            PCD(1,0, Pr10, Pi10) PCD(2,1, Pr21, Pi21) PCD(3,2, Pr32, Pi32)
            PCD(2,0, Pr20, Pi20) PCD(3,1, Pr31, Pi31) PCD(3,0, Pr30, Pi30)
            #undef PCD

            float* qo = &gQ[blockIdx.x * 8];
            qo[0] = Pd;
            qo[1] = Pr10 + Pr21 + Pr32;
            qo[2] = Pi10 + Pi21 + Pi32;
            qo[3] = Pr20 + Pr31;
            qo[4] = Pi20 + Pi31;
            qo[5] = Pr30;
            qo[6] = Pi30;
            qo[7] = 0.f;
        }
    }
}

// ============================================================
// Kernel 2: angle sweep (18001 angles, 19 bins via phase recurrence)
// ============================================================
__global__ void __launch_bounds__(128, 1) k_spec(float* __restrict__ out)
{
    __shared__ float sQ[NBIN * 8];
    const int tid = threadIdx.x;
    for (int i = tid; i < NBIN * 8; i += 128) sQ[i] = gQ[i];
    __syncthreads();

    int a = blockIdx.x * 128 + tid;
    if (a >= NANG) return;

    float th = (-90.0f + 0.01f * (float)a) * 0.017453292519943295f;
    float st = __sinf(th);
    float base = (float)(2.0 * M_PI * 0.1 / 343.0) * st;

    float dphi = base * 31.25f;
    float phi0 = dphi * (float)BIN0;
    float s1, c1, sd, cd;
    __sincosf(phi0, &s1, &c1);
    __sincosf(dphi, &sd, &cd);

    float acc = 0.0f;
    #pragma unroll
    for (int k = 0; k < NBIN; k++) {
        float c2 = fmaf(c1, c1, -s1*s1);
        float s2 = 2.0f * c1 * s1;
        float c3 = fmaf(c2, c1, -s2*s1);
        float s3 = fmaf(s2, c1,  c2*s1);
        const float* q = &sQ[k * 8];
        float denom = fmaf(2.0f,
              fmaf(q[1], c1, fmaf(q[2], s1,
              fmaf(q[3], c2, fmaf(q[4], s2,
              fmaf(q[5], c3,       q[6]*s3))))),
              q[0]) + 1e-8f;
        acc += __fdividef(1.0f, denom);
        float c1n = fmaf(c1, cd, -s1*sd);
        float s1n = fmaf(s1, cd,  c1*sd);
        c1 = c1n; s1 = s1n;
    }
    out[a] = acc * (1.0f / 19.0f);
}

extern "C" void kernel_launch(void* const* d_in, const int* in_sizes, int n_in,
                              void* d_out, int out_size)
{
    const float* x = (const float*)d_in[0];
    float* out = (float*)d_out;
    k_dft_eig<<<NBIN, 512>>>(x);
    k_spec<<<(NANG + 127) / 128, 128>>>(out);
}

// round 14
// speedup vs baseline: 1.6800x; 1.6800x over previous
#include <cuda_runtime.h>
#include <math.h>

// ---- problem constants ----
#define NFFT      512
#define HOP       256
#define NBIN      19      // rfft bins 13..31  (400 <= f < 1000 Hz, df = 31.25)
#define BIN0      13
#define NANG      18001
#define MICS      4
#define NFRM      4       // EST_NUM frames, t = 120..123
#define SAMPLE_OFF 30464  // first sample used = 119*256
#define NTCK      (NFRM * MICS * NBIN)   // 304

// DFT results X[t][c][k], layout (t*MICS+c)*NBIN + k
__device__ float2 gX[NTCK];

// ============================================================
// Kernel 1: warp-parallel windowed DFT. One warp per (t,c,bin).
// 38 blocks x 256 threads = 304 warps.  (proven: ~2.8us)
// ============================================================
__global__ void __launch_bounds__(256, 1) k_dft(const float* __restrict__ x)
{
    const int w = (blockIdx.x * 256 + threadIdx.x) >> 5;   // 0..303 exactly
    const int l = threadIdx.x & 31;

    const int t   = w / (MICS * NBIN);
    const int rem = w % (MICS * NBIN);
    const int c   = rem / NBIN;
    const int bin = (rem % NBIN) + BIN0;

    const float ANG = -0.012271846303085130f;              // -2*pi/512
    float c1, s1, cs, ss;
    __sincosf((float)((bin * l)  & 511) * ANG, &s1, &c1);
    __sincosf((float)((bin * 32) & 511) * ANG, &ss, &cs);

    const float* px = x + ((size_t)SAMPLE_OFF + (size_t)t * HOP) * MICS + c;

    float re = 0.f, im = 0.f;
    #pragma unroll
    for (int j = 0; j < 16; j++) {
        int n = l + 32 * j;
        float v = px[n * MICS] * __sinf((float)n * (float)(M_PI / 512.0));
        re = fmaf(v, c1, re);
        im = fmaf(v, s1, im);
        float cn = fmaf(c1, cs, -s1 * ss);
        float sn = fmaf(s1, cs,  c1 * ss);
        c1 = cn; s1 = sn;
    }
    #pragma unroll
    for (int off = 16; off; off >>= 1) {
        re += __shfl_down_sync(0xffffffffu, re, off);
        im += __shfl_down_sync(0xffffffffu, im, off);
    }
    if (l == 0) gX[w] = make_float2(re, im);
}

// one complex Jacobi rotation on D, eigenvalues-only (no V), compile-time (p,q)
#define ROTD(p, q) do {                                                        \
    float gr = Dr[p][q], gi = Di[p][q];                                        \
    float g2 = fmaf(gr, gr, gi * gi);                                          \
    if (g2 >= thr) {                                                           \
        float inv_g = rsqrtf(g2);                                              \
        float er = gr * inv_g, ei = gi * inv_g;                                \
        float tau = (Dr[q][q] - Dr[p][p]) * (0.5f * inv_g);                    \
        float t2  = fmaf(tau, tau, 1.f);                                       \
        float root = t2 * rsqrtf(t2);                                          \
        float tt = __fdividef((tau >= 0.f) ? -1.f : 1.f, fabsf(tau) + root);   \
        float cc = rsqrtf(fmaf(tt, tt, 1.f));                                  \
        float ssn = tt * cc;                                                   \
        float se_r = ssn * er, se_i = ssn * ei;                                \
        float ce_r = cc * er,  ce_i = cc * ei;                                 \
        _Pragma("unroll")                                                      \
        for (int i = 0; i < 4; i++) {            /* D <- D R */                \
            float pr = Dr[i][p], pi = Di[i][p];                                \
            float qr = Dr[i][q], qi = Di[i][q];                                \
            Dr[i][p] =  pr*cc + qr*se_r + qi*se_i;                             \
            Di[i][p] =  pi*cc - qr*se_i + qi*se_r;                             \
            Dr[i][q] = -pr*ssn + qr*ce_r + qi*ce_i;                            \
            Di[i][q] = -pi*ssn - qr*ce_i + qi*ce_r;                            \
        }                                                                      \
        _Pragma("unroll")                                                      \
        for (int j = 0; j < 4; j++) {            /* D <- R^H D */              \
            float pr = Dr[p][j], pi = Di[p][j];                                \
            float qr = Dr[q][j], qi = Di[q][j];                                \
            Dr[p][j] =  cc*pr + se_r*qr - se_i*qi;                             \
            Di[p][j] =  cc*pi + se_r*qi + se_i*qr;                             \
            Dr[q][j] = -ssn*pr + ce_r*qr - ce_i*qi;                            \
            Di[q][j] = -ssn*pi + ce_r*qi + ce_i*qr;                            \
        }                                                                      \
    }                                                                          \
} while (0)

// ============================================================
// Kernel 2 (fused): lanes 0..18 of warp 0 in every block compute
// the 19 noise projectors via eigenvalues-only Jacobi + polynomial
// projector P = p(A)(aA+bI); then all threads evaluate their angle.
// ============================================================
__global__ void __launch_bounds__(128, 1) k_eig_spec(float* __restrict__ out)
{
    __shared__ float sQ[NBIN * 8];
    const int tid = threadIdx.x;

    if (tid < NBIN) {
        const int f = tid;
        float xr[16], xi[16];
        #pragma unroll
        for (int i = 0; i < 16; i++) {
            float2 v = __ldcg(&gX[i * NBIN + f]);   // coalesced across lanes
            xr[i] = v.x; xi[i] = v.y;
        }

        // A[c][d] = sum_t X[t][c] conj(X[t][d])   (scale-free: projector invariant)
        float Ar[4][4], Ai[4][4];
        #pragma unroll
        for (int c = 0; c < 4; c++)
            #pragma unroll
            for (int d = 0; d <= c; d++) {
                float sr = 0.f, si = 0.f;
                #pragma unroll
                for (int t = 0; t < 4; t++) {
                    int ic = t * 4 + c, id = t * 4 + d;
                    sr = fmaf(xr[ic], xr[id], fmaf(xi[ic], xi[id], sr));
                    si = fmaf(xi[ic], xr[id], fmaf(-xr[ic], xi[id], si));
                }
                Ar[c][d] = sr;  Ai[c][d] = (c == d) ? 0.f : si;
                Ar[d][c] = sr;  Ai[d][c] = -Ai[c][d];
            }

        // working copy for eigenvalues-only Jacobi
        float Dr[4][4], Di[4][4];
        #pragma unroll
        for (int c = 0; c < 4; c++)
            #pragma unroll
            for (int d = 0; d < 4; d++) { Dr[c][d] = Ar[c][d]; Di[c][d] = Ai[c][d]; }

        float trace = Ar[0][0] + Ar[1][1] + Ar[2][2] + Ar[3][3];
        float thr   = trace * trace * 1e-14f + 1e-30f;

        for (int sweep = 0; sweep < 4; sweep++) {
            ROTD(0,1); ROTD(2,3);
            ROTD(0,2); ROTD(1,3);
            ROTD(0,3); ROTD(1,2);
        }

        float ev0 = Dr[0][0], ev1 = Dr[1][1], ev2 = Dr[2][2], ev3 = Dr[3][3];
        int r0 = (ev1 <  ev0) + (ev2 <  ev0) + (ev3 <  ev0);
        int r1 = (ev0 <= ev1) + (ev2 <  ev1) + (ev3 <  ev1);
        int r2 = (ev0 <= ev2) + (ev1 <= ev2) + (ev3 <  ev2);
        int r3 = (ev0 <= ev3) + (ev1 <= ev3) + (ev2 <= ev3);
        // lam0<=lam1<=lam2<=lam3 (ranks are a permutation by construction)
        float lam0 = (r0==0)?ev0:((r1==0)?ev1:((r2==0)?ev2:ev3));
        float lam1 = (r0==1)?ev0:((r1==1)?ev1:((r2==1)?ev2:ev3));
        float lam2 = (r0==2)?ev0:((r1==2)?ev1:((r2==2)?ev2:ev3));
        float lam3 = (r0==3)?ev0:((r1==3)?ev1:((r2==3)?ev2:ev3));

        // p(x) = (x-lam3)(x-lam2); P_noise = p(A) * (alpha*A + beta*I)
        float s  = lam3 + lam2;
        float tp = lam3 * lam2;
        float pc = (lam0 - lam3) * (lam0 - lam2);
        float pd = (lam1 - lam3) * (lam1 - lam2);
        float alpha = __fdividef(s - lam0 - lam1, pc * pd);
        float beta  = __fdividef(1.f, pc) - alpha * lam0;

        // B = A^2 - s*A + tp*I
        float Br[4][4], Bi[4][4];
        #pragma unroll
        for (int i = 0; i < 4; i++)
            #pragma unroll
            for (int j = 0; j < 4; j++) {
                float br = 0.f, bi = 0.f;
                #pragma unroll
                for (int k = 0; k < 4; k++) {
                    br = fmaf(Ar[i][k], Ar[k][j], fmaf(-Ai[i][k], Ai[k][j], br));
                    bi = fmaf(Ar[i][k], Ai[k][j], fmaf( Ai[i][k], Ar[k][j], bi));
                }
                br = fmaf(-s, Ar[i][j], br);
                bi = fmaf(-s, Ai[i][j], bi);
                if (i == j) br += tp;
                Br[i][j] = br; Bi[i][j] = bi;
            }

        // needed P entries: P[c][d] = alpha*(B*A)[c][d] + beta*B[c][d]
        #define PAE(c, d, RR, II)                                              \
            float RR = 0.f, II = 0.f;                                          \
            _Pragma("unroll")                                                  \
            for (int k2 = 0; k2 < 4; k2++) {                                   \
                RR = fmaf(Br[c][k2], Ar[k2][d], fmaf(-Bi[c][k2], Ai[k2][d], RR)); \
                II = fmaf(Br[c][k2], Ai[k2][d], fmaf( Bi[c][k2], Ar[k2][d], II)); \
            }                                                                  \
            RR = fmaf(alpha, RR, beta * Br[c][d]);                             \
            II = fmaf(alpha, II, beta * Bi[c][d]);
        PAE(1,0, Pr10, Pi10) PAE(2,1, Pr21, Pi21) PAE(3,2, Pr32, Pi32)
        PAE(2,0, Pr20, Pi20) PAE(3,1, Pr31, Pi31) PAE(3,0, Pr30, Pi30)
        #undef PAE

        // trace(P) = alpha*tr(B*A) + beta*tr(B); tr(BA) = sum Br.*Ar + Bi.*Ai
        float trBA = 0.f;
        #pragma unroll
        for (int i = 0; i < 4; i++)
            #pragma unroll
            for (int k = 0; k < 4; k++)
                trBA = fmaf(Br[i][k], Ar[i][k], fmaf(Bi[i][k], Ai[i][k], trBA));
        float q0 = fmaf(alpha, trBA, beta * (Br[0][0] + Br[1][1] + Br[2][2] + Br[3][3]));

        float* qo = &sQ[f * 8];
        qo[0] = q0;
        qo[1] = Pr10 + Pr21 + Pr32;
        qo[2] = Pi10 + Pi21 + Pi32;
        qo[3] = Pr20 + Pr31;
        qo[4] = Pi20 + Pi31;
        qo[5] = Pr30;
        qo[6] = Pi30;
        qo[7] = 0.f;
    }

    // ---- spec init (independent of sQ; warps 1-3 do this while warp 0 eigens) ----
    int a = blockIdx.x * 128 + tid;
    float th = (-90.0f + 0.01f * (float)a) * 0.017453292519943295f;
    float st = __sinf(th);
    float base = (float)(2.0 * M_PI * 0.1 / 343.0) * st;
    float dphi = base * 31.25f;
    float phi0 = dphi * (float)BIN0;
    float s1, c1, sd, cd;
    __sincosf(phi0, &s1, &c1);
    __sincosf(dphi, &sd, &cd);

    __syncthreads();

    if (a >= NANG) return;

    float acc = 0.0f;
    #pragma unroll
    for (int k = 0; k < NBIN; k++) {
        float c2 = fmaf(c1, c1, -s1*s1);
        float s2 = 2.0f * c1 * s1;
        float c3 = fmaf(c2, c1, -s2*s1);
        float s3 = fmaf(s2, c1,  c2*s1);
        const float* q = &sQ[k * 8];
        float denom = fmaf(2.0f,
              fmaf(q[1], c1, fmaf(q[2], s1,
              fmaf(q[3], c2, fmaf(q[4], s2,
              fmaf(q[5], c3,       q[6]*s3))))),
              q[0]) + 1e-8f;
        acc += __fdividef(1.0f, denom);
        float c1n = fmaf(c1, cd, -s1*sd);
        float s1n = fmaf(s1, cd,  c1*sd);
        c1 = c1n; s1 = s1n;
    }
    out[a] = acc * (1.0f / 19.0f);
}

extern "C" void kernel_launch(void* const* d_in, const int* in_sizes, int n_in,
                              void* d_out, int out_size)
{
    const float* x = (const float*)d_in[0];
    float* out = (float*)d_out;
    k_dft<<<38, 256>>>(x);
    k_eig_spec<<<(NANG + 127) / 128, 128>>>(out);
}